// round 6
// baseline (speedup 1.0000x reference)
#include <cuda_runtime.h>
#include <cstdint>

// DilateAttention: B=4, d=384 (12 heads x 32), H=W=64, 3x3 kernel, dilation 2, zero pad 2.
// q,k,v: [B, 384, 64, 64] f32. out: [B, 64, 64, 384] f32.
// Channel-split: lanes (i, i+16) hold the two 16-channel halves of one pixel;
// QK partials combined with one shfl_xor(16). K and V staged through ONE smem
// tile in two phases (zero pads persist across the restage).

#define NH  12
#define HD  32
#define HH  64
#define WW  64
#define TH  4
#define RR  (TH + 4)            // 8 halo rows
#define CC  68                  // 64 + 2 zero-pad each side
#define PS  (RR * CC)           // 544 floats per channel plane
#define SMEM_FLOATS (2 + 32 * PS + 16 + 8)
#define SCALE 0.17677669529663689f   // 32^-0.5

__device__ __forceinline__ void cp_async16(uint32_t saddr, const void* gptr) {
    asm volatile("cp.async.cg.shared.global [%0], [%1], 16;\n" :: "r"(saddr), "l"(gptr));
}
__device__ __forceinline__ void cp_commit_wait() {
    asm volatile("cp.async.commit_group;\ncp.async.wait_group 0;\n" ::: "memory");
}

__global__ __launch_bounds__(512, 2)
void dilate_attn_kernel(const float* __restrict__ q,
                        const float* __restrict__ k,
                        const float* __restrict__ v,
                        float* __restrict__ out)
{
    extern __shared__ float smem[];
    float* tile = smem + 2;   // shift so interior cp.async dst is 16B-aligned

    const int tid  = threadIdx.x;              // 0..511
    const int lane = tid & 31;
    const int wid  = tid >> 5;                 // 0..15
    const int px   = wid * 16 + (lane & 15);   // 0..255 pixel in tile
    const int row  = px >> 6;                  // 0..3
    const int col  = px & 63;                  // 0..63
    const int ch0  = (lane & 16);              // 0 or 16: channel half base

    const int h0   = blockIdx.x * TH;
    const int bh   = blockIdx.y;               // 0..47
    const int b    = bh / NH;
    const int head = bh - b * NH;
    const size_t base = ((size_t)b * 384 + (size_t)head * HD) * (HH * WW);

    // ---- staging assignment: half a halo row per thread (32ch x 8r x 2 halves) ----
    const int sc = tid >> 4;                   // channel 0..31
    const int sr = (tid >> 1) & 7;             // halo row 0..7
    const int hf = tid & 1;                    // row half 0/1
    const int gh = h0 - 2 + sr;
    const bool inb = (unsigned)gh < HH;
    // +16 plane offset for channels >= 16: keeps the two half-warps on disjoint
    // bank halves during compute (16*544 == 0 mod 32 banks otherwise)
    const int rowbase = sc * PS + ((sc >= 16) ? 16 : 0) + sr * CC;
    const size_t goff = base + (size_t)sc * (HH * WW) + gh * WW + hf * 32;
    const uint32_t s_int =
        (uint32_t)__cvta_generic_to_shared(&tile[rowbase + 2 + hf * 32]);

    // ---- phase K: stage k tile ----
    if (inb) {
        #pragma unroll
        for (int j = 0; j < 8; j++) cp_async16(s_int + j * 16, k + goff + j * 4);
        if (hf == 0) { tile[rowbase + 0] = 0.f;  tile[rowbase + 1] = 0.f; }
        else         { tile[rowbase + 66] = 0.f; tile[rowbase + 67] = 0.f; }
    } else {
        #pragma unroll
        for (int j = 0; j < CC / 2; j++) tile[rowbase + hf * 34 + j] = 0.f;
    }

    // ---- q (16 channels) into registers while cp.async streams ----
    const int h = h0 + row;
    float qr[16];
    {
        const float* qp = q + base + (size_t)ch0 * (HH * WW) + h * WW + col;
        #pragma unroll
        for (int c = 0; c < 16; c++) qr[c] = qp[(size_t)c * (HH * WW)];
    }

    cp_commit_wait();
    __syncthreads();

    // ---- logits: 16-wide partial dot + shuffle-combine across lane pairs ----
    const int chbase = ch0 * PS + (ch0 ? 16 : 0);
    float lg[9];
    #pragma unroll
    for (int kp = 0; kp < 9; kp++) {
        const int di = kp / 3;
        const int dj = kp - di * 3;
        const float* kr = &tile[chbase + (row + 2 * di) * CC + col + 2 * dj];
        float d0 = 0.f, d1 = 0.f;
        #pragma unroll
        for (int c = 0; c < 16; c += 2) {
            d0 = fmaf(qr[c],     kr[(c)     * PS], d0);
            d1 = fmaf(qr[c + 1], kr[(c + 1) * PS], d1);
        }
        const float partial = d0 + d1;
        const float full = partial + __shfl_xor_sync(0xffffffffu, partial, 16);
        lg[kp] = full * SCALE;             // OOB neighbor: k==0 in smem -> logit 0
    }

    // ---- softmax over 9 (redundant in both halves; cheap) ----
    float m = lg[0];
    #pragma unroll
    for (int kp = 1; kp < 9; kp++) m = fmaxf(m, lg[kp]);
    float p[9];
    float s = 0.f;
    #pragma unroll
    for (int kp = 0; kp < 9; kp++) { p[kp] = __expf(lg[kp] - m); s += p[kp]; }
    const float inv = __fdividef(1.f, s);

    // ---- phase V: restage same buffer with v (pads/OOB rows stay zero) ----
    __syncthreads();                       // all done reading k
    if (inb) {
        #pragma unroll
        for (int j = 0; j < 8; j++) cp_async16(s_int + j * 16, v + goff + j * 4);
    }
    cp_commit_wait();
    __syncthreads();

    // ---- weighted v from smem (conflict-free, same addressing as QK) ----
    float acc[16];
    #pragma unroll
    for (int c = 0; c < 16; c++) acc[c] = 0.f;

    #pragma unroll
    for (int kp = 0; kp < 9; kp++) {
        const int di = kp / 3;
        const int dj = kp - di * 3;
        const float pw = p[kp];
        const float* vr = &tile[chbase + (row + 2 * di) * CC + col + 2 * dj];
        #pragma unroll
        for (int c = 0; c < 16; c++)
            acc[c] = fmaf(pw, vr[c * PS], acc[c]);
    }

    // ---- contiguous 64B store per thread (4 x STG.128) ----
    const size_t obase = (((size_t)b * HH + h) * WW + col) * 384
                         + (size_t)head * HD + ch0;
    float4* o4 = (float4*)(out + obase);
    #pragma unroll
    for (int i = 0; i < 4; i++) {
        float4 t;
        t.x = acc[4 * i + 0] * inv;
        t.y = acc[4 * i + 1] * inv;
        t.z = acc[4 * i + 2] * inv;
        t.w = acc[4 * i + 3] * inv;
        o4[i] = t;
    }
}

extern "C" void kernel_launch(void* const* d_in, const int* in_sizes, int n_in,
                              void* d_out, int out_size)
{
    const float* q = (const float*)d_in[0];
    const float* k = (const float*)d_in[1];
    const float* v = (const float*)d_in[2];
    float* out = (float*)d_out;

    const int smem_bytes = SMEM_FLOATS * sizeof(float);   // ~69.8 KB
    cudaFuncSetAttribute(dilate_attn_kernel,
                         cudaFuncAttributeMaxDynamicSharedMemorySize, smem_bytes);

    dim3 block(512, 1, 1);
    dim3 grid(HH / TH, 4 * NH, 1);        // (16, 48)
    dilate_attn_kernel<<<grid, block, smem_bytes>>>(q, k, v, out);
}

// round 7
// speedup vs baseline: 1.1404x; 1.1404x over previous
#include <cuda_runtime.h>
#include <cstdint>

// DilateAttention: B=4, d=384 (12 heads x 32), H=W=64, 3x3 kernel, dilation 2, zero pad 2.
// q,k,v: [B, 384, 64, 64] f32. out: [B, 64, 64, 384] f32.
// R3 structure + channel-halved software pipeline: v restage for ch0-15 is
// issued as soon as QK no longer needs k ch0-15, overlapping QK ch16-31 and
// softmax; v ch16-31 copy hides behind AV ch0-15.

#define NH  12
#define HD  32
#define HH  64
#define WW  64
#define TH  4
#define RR  (TH + 4)            // 8 rows incl. halo
#define CC  68                  // 64 cols + 2 zero-pad each side
#define TILE_FLOATS (HD * RR * CC)   // 17408
#define SMEM_FLOATS (TILE_FLOATS + 4)
#define SCALE 0.17677669529663689f   // 32^-0.5

__device__ __forceinline__ void cp_async16(uint32_t saddr, const void* gptr) {
    asm volatile("cp.async.cg.shared.global [%0], [%1], 16;\n" :: "r"(saddr), "l"(gptr));
}
__device__ __forceinline__ void cp_commit() {
    asm volatile("cp.async.commit_group;\n" ::: "memory");
}
__device__ __forceinline__ void cp_wait0() {
    asm volatile("cp.async.wait_group 0;\n" ::: "memory");
}

__global__ __launch_bounds__(256, 3)
void dilate_attn_kernel(const float* __restrict__ q,
                        const float* __restrict__ k,
                        const float* __restrict__ v,
                        float* __restrict__ out)
{
    extern __shared__ float smem[];
    // tile[c][r][cc] at smem+2: interior (cc=2) byte addr = row*272 + 16 -> 16B aligned
    float* tile = smem + 2;

    const int tx  = threadIdx.x;       // 0..63 = w
    const int ty  = threadIdx.y;       // 0..3
    const int tid = ty * 64 + tx;

    const int h0   = blockIdx.x * TH;
    const int bh   = blockIdx.y;       // 0..47
    const int b    = bh / NH;
    const int head = bh - b * NH;
    const size_t base = ((size_t)b * 384 + (size_t)head * HD) * (HH * WW);

    // ---- staging map: one halo row per thread; tid<128 <=> channel<16 ----
    const int sc = tid >> 3;           // channel 0..31
    const int sr = tid & 7;            // halo row 0..7
    const int gh = h0 - 2 + sr;
    const int rowoff = (sc * RR + sr) * CC;
    const bool inb = (unsigned)gh < HH;
    const bool lowhalf = (sc < 16);
    const float* gk = k + base + (size_t)sc * (HH * WW) + gh * WW;
    const float* gv = v + base + (size_t)sc * (HH * WW) + gh * WW;
    const uint32_t s_int = (uint32_t)__cvta_generic_to_shared(&tile[rowoff + 2]);

    // ---- stage k tile (zero pads persist through the v restage) ----
    if (inb) {
        #pragma unroll
        for (int j = 0; j < 16; j++) cp_async16(s_int + j * 16, gk + j * 4);
        tile[rowoff + 0] = 0.f; tile[rowoff + 1] = 0.f;
        tile[rowoff + 66] = 0.f; tile[rowoff + 67] = 0.f;
    } else {
        #pragma unroll
        for (int j = 0; j < CC; j++) tile[rowoff + j] = 0.f;
    }
    cp_commit();

    // q into registers while cp.async streams
    const int h = h0 + ty;
    float qr[HD];
    {
        const float* qp = q + base + h * WW + tx;
        #pragma unroll
        for (int c = 0; c < HD; c++) qr[c] = qp[(size_t)c * (HH * WW)];
    }

    cp_wait0();
    __syncthreads();                       // bar1: k tile visible

    // ---- QK half 1: channels 0..15 partial logits ----
    float lg[9];
    #pragma unroll
    for (int kp = 0; kp < 9; kp++) {
        const int di = kp / 3;
        const int dj = kp - di * 3;
        const float* kr = &tile[(ty + 2 * di) * CC + tx + 2 * dj];
        float d0 = 0.f, d1 = 0.f;
        #pragma unroll
        for (int c = 0; c < 16; c += 2) {
            d0 = fmaf(qr[c],     kr[(c)     * (RR * CC)], d0);
            d1 = fmaf(qr[c + 1], kr[(c + 1) * (RR * CC)], d1);
        }
        lg[kp] = d0 + d1;
    }

    __syncthreads();                       // bar2: k planes 0-15 dead

    // low-half threads start restaging v into planes 0-15 NOW
    if (lowhalf) {
        if (inb) {
            #pragma unroll
            for (int j = 0; j < 16; j++) cp_async16(s_int + j * 16, gv + j * 4);
        }
        cp_commit();
    }

    // ---- QK half 2: channels 16..31 (overlaps the v half-1 copy) ----
    #pragma unroll
    for (int kp = 0; kp < 9; kp++) {
        const int di = kp / 3;
        const int dj = kp - di * 3;
        const float* kr = &tile[(16 * RR * CC) + (ty + 2 * di) * CC + tx + 2 * dj];
        float d0 = 0.f, d1 = 0.f;
        #pragma unroll
        for (int c = 0; c < 16; c += 2) {
            d0 = fmaf(qr[16 + c],     kr[(c)     * (RR * CC)], d0);
            d1 = fmaf(qr[16 + c + 1], kr[(c + 1) * (RR * CC)], d1);
        }
        lg[kp] = (lg[kp] + d0 + d1) * SCALE;   // OOB neighbor: k==0 -> logit 0
    }

    // ---- softmax over 9 ----
    float m = lg[0];
    #pragma unroll
    for (int kp = 1; kp < 9; kp++) m = fmaxf(m, lg[kp]);
    float p[9];
    float s = 0.f;
    #pragma unroll
    for (int kp = 0; kp < 9; kp++) { p[kp] = __expf(lg[kp] - m); s += p[kp]; }
    const float inv = __fdividef(1.f, s);

    __syncthreads();                       // bar3: k planes 16-31 dead

    // high-half threads restage v into planes 16-31 (hides behind AV half 1)
    if (!lowhalf) {
        if (inb) {
            #pragma unroll
            for (int j = 0; j < 16; j++) cp_async16(s_int + j * 16, gv + j * 4);
        }
        cp_commit();
    }

    if (lowhalf) cp_wait0();               // own v copies (planes 0-15) done
    __syncthreads();                       // bar4: v planes 0-15 visible

    // ---- AV half 1: channels 0..15 ----
    float acc[HD];
    #pragma unroll
    for (int c = 0; c < HD; c++) acc[c] = 0.f;
    #pragma unroll
    for (int kp = 0; kp < 9; kp++) {
        const int di = kp / 3;
        const int dj = kp - di * 3;
        const float pw = p[kp];
        const float* vr = &tile[(ty + 2 * di) * CC + tx + 2 * dj];
        #pragma unroll
        for (int c = 0; c < 16; c++)
            acc[c] = fmaf(pw, vr[c * (RR * CC)], acc[c]);
    }

    if (!lowhalf) cp_wait0();              // own v copies (planes 16-31) done
    __syncthreads();                       // bar5: v planes 16-31 visible

    // ---- AV half 2: channels 16..31 ----
    #pragma unroll
    for (int kp = 0; kp < 9; kp++) {
        const int di = kp / 3;
        const int dj = kp - di * 3;
        const float pw = p[kp];
        const float* vr = &tile[(16 * RR * CC) + (ty + 2 * di) * CC + tx + 2 * dj];
        #pragma unroll
        for (int c = 0; c < 16; c++)
            acc[16 + c] = fmaf(pw, vr[c * (RR * CC)], acc[16 + c]);
    }

    // ---- transpose through smem for coalesced 128B output stores ----
    __syncthreads();                       // bar6: v dead before overwrite
    float* ts = smem;                      // 256*33 = 8448 floats < SMEM_FLOATS
    #pragma unroll
    for (int c = 0; c < HD; c++)
        ts[tid * 33 + c] = acc[c] * inv;
    __syncwarp();                          // each warp reads only its own 32 pixels

    const int lane  = tid & 31;            // becomes channel
    const int wbase = tid & ~31;
    #pragma unroll 4
    for (int pp = 0; pp < 32; pp++) {
        const int pid = wbase + pp;
        const int h2 = h0 + (pid >> 6);
        const int w2 = pid & 63;
        out[(((size_t)b * HH + h2) * WW + w2) * 384 + (size_t)head * HD + lane]
            = ts[pid * 33 + lane];
    }
}

extern "C" void kernel_launch(void* const* d_in, const int* in_sizes, int n_in,
                              void* d_out, int out_size)
{
    const float* q = (const float*)d_in[0];
    const float* k = (const float*)d_in[1];
    const float* v = (const float*)d_in[2];
    float* out = (float*)d_out;

    const int smem_bytes = SMEM_FLOATS * sizeof(float);   // 69648
    cudaFuncSetAttribute(dilate_attn_kernel,
                         cudaFuncAttributeMaxDynamicSharedMemorySize, smem_bytes);

    dim3 block(64, 4, 1);
    dim3 grid(HH / TH, 4 * NH, 1);        // (16, 48)
    dilate_attn_kernel<<<grid, block, smem_bytes>>>(q, k, v, out);
}